// round 1
// baseline (speedup 1.0000x reference)
#include <cuda_runtime.h>
#include <cuda_bf16.h>

// Problem constants (match reference)
#define BB 32
#define LL 4096
#define DD 128
#define NN1 4      // N-1 context slots
#define VV 128

// Scratch table: T[k][tok][v], 4*128*128 floats = 256 KB (device global, no alloc)
__device__ float g_T[NN1 * VV * VV];

// ---------------------------------------------------------------------------
// Kernel 1: build T[k][tok][v] = sum_d emb[tok][d] * W[v][k*128 + d]
// grid = 128 blocks (one per tok), 512 threads (k = tid>>7, v = tid&127)
// ---------------------------------------------------------------------------
__global__ void build_table_kernel(const float* __restrict__ emb,
                                   const float* __restrict__ W) {
    const int tok = blockIdx.x;
    __shared__ float e[DD];
    if (threadIdx.x < DD) e[threadIdx.x] = emb[tok * DD + threadIdx.x];
    __syncthreads();

    const int k = threadIdx.x >> 7;      // 0..3
    const int v = threadIdx.x & 127;     // 0..127

    const float4* w4 = reinterpret_cast<const float4*>(W + (size_t)v * (NN1 * DD) + k * DD);
    float acc = 0.0f;
#pragma unroll
    for (int i = 0; i < DD / 4; i++) {
        float4 w = __ldg(&w4[i]);
        acc += w.x * e[4 * i + 0];
        acc += w.y * e[4 * i + 1];
        acc += w.z * e[4 * i + 2];
        acc += w.w * e[4 * i + 3];
    }
    g_T[(k * VV + tok) * VV + v] = acc;
}

// ---------------------------------------------------------------------------
// Kernel 2: gather-sum. One warp per (b, j) position; lane handles 4 v's.
// out[pos*128 + v] = T[0][t0][v] + T[1][t1][v] + T[2][t2][v] + T[3][t3][v] + b[v]
// positions with j < 4 emit just b[v] (context is all-zero in reference).
// ---------------------------------------------------------------------------
__global__ void __launch_bounds__(256)
ngram_sum_kernel(const int* __restrict__ x,
                 const float* __restrict__ bvec,
                 float* __restrict__ out) {
    const int warps_per_blk = blockDim.x >> 5;
    const int pos  = blockIdx.x * warps_per_blk + (threadIdx.x >> 5);
    const int lane = threadIdx.x & 31;
    if (pos >= BB * LL) return;

    const int b = pos >> 12;          // / 4096
    const int j = pos & (LL - 1);     // % 4096

    float4* out4 = reinterpret_cast<float4*>(out + (size_t)pos * VV);
    const float4 bb = reinterpret_cast<const float4*>(bvec)[lane];

    if (j < NN1) {
        out4[lane] = bb;
        return;
    }

    const int* xr = x + b * LL + (j - NN1);
    const int t0 = __ldg(xr + 0);
    const int t1 = __ldg(xr + 1);
    const int t2 = __ldg(xr + 2);
    const int t3 = __ldg(xr + 3);

    const float4* r0 = reinterpret_cast<const float4*>(g_T + (0 * VV + t0) * VV);
    const float4* r1 = reinterpret_cast<const float4*>(g_T + (1 * VV + t1) * VV);
    const float4* r2 = reinterpret_cast<const float4*>(g_T + (2 * VV + t2) * VV);
    const float4* r3 = reinterpret_cast<const float4*>(g_T + (3 * VV + t3) * VV);

    float4 a0 = __ldg(&r0[lane]);
    float4 a1 = __ldg(&r1[lane]);
    float4 a2 = __ldg(&r2[lane]);
    float4 a3 = __ldg(&r3[lane]);

    float4 s;
    s.x = (a0.x + a1.x) + (a2.x + a3.x) + bb.x;
    s.y = (a0.y + a1.y) + (a2.y + a3.y) + bb.y;
    s.z = (a0.z + a1.z) + (a2.z + a3.z) + bb.z;
    s.w = (a0.w + a1.w) + (a2.w + a3.w) + bb.w;

    out4[lane] = s;
}

// ---------------------------------------------------------------------------
// Launch. Inputs (metadata order): x(int32 B*L), emb(f32 V*D), W(f32 V*4D),
// b(f32 V). Output: f32 B*L*V.
// ---------------------------------------------------------------------------
extern "C" void kernel_launch(void* const* d_in, const int* in_sizes, int n_in,
                              void* d_out, int out_size) {
    const int*   x    = (const int*)d_in[0];
    const float* emb  = (const float*)d_in[1];
    const float* W    = (const float*)d_in[2];
    const float* bvec = (const float*)d_in[3];
    float* out = (float*)d_out;

    build_table_kernel<<<VV, 512>>>(emb, W);

    const int positions = BB * LL;              // 131072
    const int warps_per_blk = 256 / 32;         // 8
    const int blocks = positions / warps_per_blk; // 16384
    ngram_sum_kernel<<<blocks, 256>>>(x, bvec, out);
}

// round 2
// speedup vs baseline: 1.0801x; 1.0801x over previous
#include <cuda_runtime.h>
#include <cuda_fp16.h>

// Problem constants (match reference)
#define BB 32
#define LL 4096
#define DD 128
#define NN1 4      // N-1 context slots
#define VV 128

// fp16 lookup table: T[k][tok][v], 4*128*128 halves = 128 KB (L1-resident)
__device__ __half g_Th[NN1 * VV * VV];

// ---------------------------------------------------------------------------
// Kernel 1: build T[k][tok][v] = sum_d emb[tok][d] * W[v][k*128 + d]
// grid = 64 blocks, each owns 2 tokens. 512 threads: k = tid>>7, v = tid&127.
// W row chunk read ONCE per thread (float4), reused for both tokens.
// emb rows staged in smem, broadcast LDS (conflict-free).
// ---------------------------------------------------------------------------
#define TOKS_PER_BLK 2
__global__ void __launch_bounds__(512)
build_table_kernel(const float* __restrict__ emb,
                   const float* __restrict__ W) {
    const int tok0 = blockIdx.x * TOKS_PER_BLK;
    __shared__ float e[TOKS_PER_BLK][DD];

    // cooperative load of TOKS_PER_BLK*128 = 256 floats (coalesced)
    if (threadIdx.x < TOKS_PER_BLK * DD) {
        int t = threadIdx.x / DD;
        int d = threadIdx.x % DD;
        e[t][d] = emb[(tok0 + t) * DD + d];
    }
    __syncthreads();

    const int k = threadIdx.x >> 7;      // 0..3
    const int v = threadIdx.x & 127;     // 0..127

    const float4* w4 = reinterpret_cast<const float4*>(W + (size_t)v * (NN1 * DD) + k * DD);
    const float4* e4_0 = reinterpret_cast<const float4*>(e[0]);
    const float4* e4_1 = reinterpret_cast<const float4*>(e[1]);

    float acc0 = 0.0f, acc1 = 0.0f;
#pragma unroll
    for (int i = 0; i < DD / 4; i++) {
        float4 w  = __ldg(&w4[i]);
        float4 a  = e4_0[i];
        float4 bb = e4_1[i];
        acc0 += w.x * a.x + w.y * a.y + w.z * a.z + w.w * a.w;
        acc1 += w.x * bb.x + w.y * bb.y + w.z * bb.z + w.w * bb.w;
    }

    // stores coalesced over v (consecutive lanes -> consecutive halves)
    g_Th[(k * VV + tok0 + 0) * VV + v] = __float2half_rn(acc0);
    g_Th[(k * VV + tok0 + 1) * VV + v] = __float2half_rn(acc1);
}

// ---------------------------------------------------------------------------
// Kernel 2: gather-sum. One warp per (b, j) position; lane handles v=lane*4..+3.
// Table rows are fp16 (256 B/row): lane loads uint2 (4 halves) per row.
// Accumulate in fp32, add bias, store float4.
// ---------------------------------------------------------------------------
__global__ void __launch_bounds__(256)
ngram_sum_kernel(const int* __restrict__ x,
                 const float* __restrict__ bvec,
                 float* __restrict__ out) {
    const int warps_per_blk = blockDim.x >> 5;
    const int pos  = blockIdx.x * warps_per_blk + (threadIdx.x >> 5);
    const int lane = threadIdx.x & 31;
    if (pos >= BB * LL) return;

    const int b = pos >> 12;          // / 4096
    const int j = pos & (LL - 1);     // % 4096

    float4* out4 = reinterpret_cast<float4*>(out + (size_t)pos * VV);
    const float4 bb = reinterpret_cast<const float4*>(bvec)[lane];

    if (j < NN1) {
        out4[lane] = bb;
        return;
    }

    const int* xr = x + b * LL + (j - NN1);
    const int t0 = __ldg(xr + 0);
    const int t1 = __ldg(xr + 1);
    const int t2 = __ldg(xr + 2);
    const int t3 = __ldg(xr + 3);

    const uint2* r0 = reinterpret_cast<const uint2*>(g_Th + (0 * VV + t0) * VV);
    const uint2* r1 = reinterpret_cast<const uint2*>(g_Th + (1 * VV + t1) * VV);
    const uint2* r2 = reinterpret_cast<const uint2*>(g_Th + (2 * VV + t2) * VV);
    const uint2* r3 = reinterpret_cast<const uint2*>(g_Th + (3 * VV + t3) * VV);

    uint2 u0 = __ldg(&r0[lane]);
    uint2 u1 = __ldg(&r1[lane]);
    uint2 u2 = __ldg(&r2[lane]);
    uint2 u3 = __ldg(&r3[lane]);

    float2 f0a = __half22float2(*reinterpret_cast<__half2*>(&u0.x));
    float2 f0b = __half22float2(*reinterpret_cast<__half2*>(&u0.y));
    float2 f1a = __half22float2(*reinterpret_cast<__half2*>(&u1.x));
    float2 f1b = __half22float2(*reinterpret_cast<__half2*>(&u1.y));
    float2 f2a = __half22float2(*reinterpret_cast<__half2*>(&u2.x));
    float2 f2b = __half22float2(*reinterpret_cast<__half2*>(&u2.y));
    float2 f3a = __half22float2(*reinterpret_cast<__half2*>(&u3.x));
    float2 f3b = __half22float2(*reinterpret_cast<__half2*>(&u3.y));

    float4 s;
    s.x = (f0a.x + f1a.x) + (f2a.x + f3a.x) + bb.x;
    s.y = (f0a.y + f1a.y) + (f2a.y + f3a.y) + bb.y;
    s.z = (f0b.x + f1b.x) + (f2b.x + f3b.x) + bb.z;
    s.w = (f0b.y + f1b.y) + (f2b.y + f3b.y) + bb.w;

    out4[lane] = s;
}

// ---------------------------------------------------------------------------
// Launch. Inputs (metadata order): x(int32 B*L), emb(f32 V*D), W(f32 V*4D),
// b(f32 V). Output: f32 B*L*V.
// ---------------------------------------------------------------------------
extern "C" void kernel_launch(void* const* d_in, const int* in_sizes, int n_in,
                              void* d_out, int out_size) {
    const int*   x    = (const int*)d_in[0];
    const float* emb  = (const float*)d_in[1];
    const float* W    = (const float*)d_in[2];
    const float* bvec = (const float*)d_in[3];
    float* out = (float*)d_out;

    build_table_kernel<<<VV / TOKS_PER_BLK, 512>>>(emb, W);

    const int positions = BB * LL;                 // 131072
    const int warps_per_blk = 256 / 32;            // 8
    const int blocks = positions / warps_per_blk;  // 16384
    ngram_sum_kernel<<<blocks, 256>>>(x, bvec, out);
}

// round 3
// speedup vs baseline: 1.5023x; 1.3908x over previous
#include <cuda_runtime.h>
#include <cuda_fp16.h>

// Problem constants (match reference)
#define BB 32
#define LL 4096
#define DD 128
#define NN1 4      // N-1 context slots
#define VV 128

// fp16 lookup table: T[k][tok][v], 4*128*128 halves = 128 KB (L1-resident).
// Bias is pre-folded into the k=0 slice.
__device__ __half g_Th[NN1 * VV * VV];

// ---------------------------------------------------------------------------
// Kernel 1: build T[k][tok][v] = sum_d emb[tok][d] * W[v][k*128+d]  (+ b[v] at k=0)
// grid = (128 toks, 8 v-groups), 64 threads = 4 k * 16 v.
// W slice (16 rows * 2KB = 32KB) staged in smem via coalesced float4 copy.
// ---------------------------------------------------------------------------
#define VPB 16                      // v-rows per block
#define WPAD 4                      // smem row pad (floats) to break bank conflicts
__global__ void __launch_bounds__(64)
build_table_kernel(const float* __restrict__ emb,
                   const float* __restrict__ W,
                   const float* __restrict__ bvec) {
    const int tok = blockIdx.x;
    const int v0  = blockIdx.y * VPB;

    __shared__ float e[DD];
    __shared__ float sw[VPB][NN1 * DD + WPAD];

    // emb row: 128 floats, 64 threads -> 2 each (coalesced)
    e[threadIdx.x]      = emb[tok * DD + threadIdx.x];
    e[threadIdx.x + 64] = emb[tok * DD + threadIdx.x + 64];

    // W slice rows v0..v0+15 are contiguous: 16*512 floats = 2048 float4
    const float4* wsrc = reinterpret_cast<const float4*>(W + (size_t)v0 * (NN1 * DD));
#pragma unroll
    for (int i = 0; i < 32; i++) {
        int idx = i * 64 + threadIdx.x;          // float4 index, coalesced
        float4 w = __ldg(&wsrc[idx]);
        int vi = idx >> 7;                       // 128 float4 per row
        int c  = idx & 127;
        *reinterpret_cast<float4*>(&sw[vi][c * 4]) = w;
    }
    __syncthreads();

    const int k  = threadIdx.x >> 4;             // 0..3
    const int vi = threadIdx.x & 15;             // 0..15
    const float* wrow = &sw[vi][k * DD];

    float acc = (k == 0) ? __ldg(&bvec[v0 + vi]) : 0.0f;
#pragma unroll
    for (int d = 0; d < DD; d += 4) {
        acc += wrow[d + 0] * e[d + 0];
        acc += wrow[d + 1] * e[d + 1];
        acc += wrow[d + 2] * e[d + 2];
        acc += wrow[d + 3] * e[d + 3];
    }
    g_Th[(k * VV + tok) * VV + v0 + vi] = __float2half_rn(acc);
}

// ---------------------------------------------------------------------------
// Kernel 2: gather-sum. One warp per TWO consecutive positions (j0 even, so
// both positions are on the same side of the j<4 boundary). Lane handles
// v = lane*4..lane*4+3 via uint2 (4 fp16) per table row.
// ---------------------------------------------------------------------------
__device__ __forceinline__ float4 combine4(uint2 u0, uint2 u1, uint2 u2, uint2 u3) {
    __half2 p0x = __hadd2(*reinterpret_cast<__half2*>(&u0.x),
                          *reinterpret_cast<__half2*>(&u1.x));
    __half2 p0y = __hadd2(*reinterpret_cast<__half2*>(&u0.y),
                          *reinterpret_cast<__half2*>(&u1.y));
    __half2 p1x = __hadd2(*reinterpret_cast<__half2*>(&u2.x),
                          *reinterpret_cast<__half2*>(&u3.x));
    __half2 p1y = __hadd2(*reinterpret_cast<__half2*>(&u2.y),
                          *reinterpret_cast<__half2*>(&u3.y));
    float2 f0 = __half22float2(p0x);
    float2 f1 = __half22float2(p0y);
    float2 f2 = __half22float2(p1x);
    float2 f3 = __half22float2(p1y);
    float4 s;
    s.x = f0.x + f2.x;
    s.y = f0.y + f2.y;
    s.z = f1.x + f3.x;
    s.w = f1.y + f3.y;
    return s;
}

__global__ void __launch_bounds__(256)
ngram_sum_kernel(const int* __restrict__ x,
                 const float* __restrict__ bvec,
                 float* __restrict__ out) {
    const int warp = blockIdx.x * (blockDim.x >> 5) + (threadIdx.x >> 5);
    const int lane = threadIdx.x & 31;
    const int pos0 = warp << 1;                 // two consecutive positions
    if (pos0 >= BB * LL) return;

    const int b  = pos0 >> 12;                  // / 4096
    const int j0 = pos0 & (LL - 1);             // % 4096  (even)

    float4* out0 = reinterpret_cast<float4*>(out + (size_t)pos0 * VV);
    float4* out1 = reinterpret_cast<float4*>(out + (size_t)(pos0 + 1) * VV);

    if (j0 < NN1) {                             // j0 in {0,2}: both bias-only
        float4 bb = reinterpret_cast<const float4*>(bvec)[lane];
        out0[lane] = bb;
        out1[lane] = bb;
        return;
    }

    const int* xr = x + b * LL + (j0 - NN1);
    const int t0 = __ldg(xr + 0);
    const int t1 = __ldg(xr + 1);
    const int t2 = __ldg(xr + 2);
    const int t3 = __ldg(xr + 3);
    const int t4 = __ldg(xr + 4);

    const uint2* T = reinterpret_cast<const uint2*>(g_Th);  // 32 uint2 per row
    // position j0: tokens t0..t3; position j0+1: tokens t1..t4
    uint2 a0 = __ldg(&T[(0 * VV + t0) * 32 + lane]);
    uint2 a1 = __ldg(&T[(1 * VV + t1) * 32 + lane]);
    uint2 a2 = __ldg(&T[(2 * VV + t2) * 32 + lane]);
    uint2 a3 = __ldg(&T[(3 * VV + t3) * 32 + lane]);
    uint2 c0 = __ldg(&T[(0 * VV + t1) * 32 + lane]);
    uint2 c1 = __ldg(&T[(1 * VV + t2) * 32 + lane]);
    uint2 c2 = __ldg(&T[(2 * VV + t3) * 32 + lane]);
    uint2 c3 = __ldg(&T[(3 * VV + t4) * 32 + lane]);

    out0[lane] = combine4(a0, a1, a2, a3);
    out1[lane] = combine4(c0, c1, c2, c3);
}

// ---------------------------------------------------------------------------
// Launch. Inputs (metadata order): x(int32 B*L), emb(f32 V*D), W(f32 V*4D),
// b(f32 V). Output: f32 B*L*V.
// ---------------------------------------------------------------------------
extern "C" void kernel_launch(void* const* d_in, const int* in_sizes, int n_in,
                              void* d_out, int out_size) {
    const int*   x    = (const int*)d_in[0];
    const float* emb  = (const float*)d_in[1];
    const float* W    = (const float*)d_in[2];
    const float* bvec = (const float*)d_in[3];
    float* out = (float*)d_out;

    dim3 bgrid(VV, VV / VPB);                   // (128, 8)
    build_table_kernel<<<bgrid, 64>>>(emb, W, bvec);

    const int positions = BB * LL;              // 131072
    const int warps = positions / 2;            // 65536
    const int blocks = warps / 8;               // 8192 (8 warps/block)
    ngram_sum_kernel<<<blocks, 256>>>(x, bvec, out);
}

// round 4
// speedup vs baseline: 1.6427x; 1.0935x over previous
#include <cuda_runtime.h>
#include <cuda_fp16.h>

// Problem constants (match reference)
#define BB 32
#define LL 4096
#define DD 128
#define NN1 4      // N-1 context slots
#define VV 128

// fp16 lookup table: T[k][tok][v], 4*128*128 halves = 128 KB (L1-resident).
// Bias is pre-folded into the k=0 slice.
__device__ __half g_Th[NN1 * VV * VV];

// ---------------------------------------------------------------------------
// Kernel 1: T[k][tok][v] = sum_d emb[tok][d] * W[v][k*128+d]  (+ b[v] at k=0)
// grid = (8 v-groups, 16 tok-groups of 8), 256 threads.
// Each block reads its 32KB W slice ONCE (coalesced float4 -> smem) and 8 emb
// rows, then thread (k, vi, tp) computes 2 toks. Total W traffic: 4 MB.
// ---------------------------------------------------------------------------
#define VPB 16      // v-rows per block
#define TPB 8       // toks per block
#define WPAD 4      // smem row pad (floats)

__global__ void __launch_bounds__(256)
build_table_kernel(const float* __restrict__ emb,
                   const float* __restrict__ W,
                   const float* __restrict__ bvec) {
    const int v0   = blockIdx.x * VPB;
    const int tok0 = blockIdx.y * TPB;

    __shared__ float sw[VPB][NN1 * DD + WPAD];
    __shared__ float e[TPB][DD + WPAD];

    // W slice: 16 rows * 512 floats = 2048 float4, coalesced
    const float4* wsrc = reinterpret_cast<const float4*>(W + (size_t)v0 * (NN1 * DD));
#pragma unroll
    for (int i = 0; i < 8; i++) {
        int idx = i * 256 + threadIdx.x;
        float4 w = __ldg(&wsrc[idx]);
        int vi = idx >> 7;                 // 128 float4 per row
        int c  = idx & 127;
        *reinterpret_cast<float4*>(&sw[vi][c * 4]) = w;
    }
    // emb: 8 rows * 128 floats = 256 float4, one per thread
    {
        const float4* esrc = reinterpret_cast<const float4*>(emb + (size_t)tok0 * DD);
        float4 ev = __ldg(&esrc[threadIdx.x]);
        int t = threadIdx.x >> 5;
        int c = threadIdx.x & 31;
        *reinterpret_cast<float4*>(&e[t][c * 4]) = ev;
    }
    __syncthreads();

    const int k  = threadIdx.x >> 6;          // 0..3
    const int vi = (threadIdx.x >> 2) & 15;   // 0..15
    const int tp = threadIdx.x & 3;           // 0..3  (toks tp and tp+4)

    const float* wrow = &sw[vi][k * DD];
    float acc0 = 0.0f, acc1 = 0.0f;
#pragma unroll
    for (int d = 0; d < DD; d += 4) {
        float4 w  = *reinterpret_cast<const float4*>(&wrow[d]);
        float4 ea = *reinterpret_cast<const float4*>(&e[tp][d]);
        float4 eb = *reinterpret_cast<const float4*>(&e[tp + 4][d]);
        acc0 += w.x * ea.x + w.y * ea.y + w.z * ea.z + w.w * ea.w;
        acc1 += w.x * eb.x + w.y * eb.y + w.z * eb.z + w.w * eb.w;
    }
    if (k == 0) {
        float bb = __ldg(&bvec[v0 + vi]);
        acc0 += bb;
        acc1 += bb;
    }
    g_Th[(k * VV + tok0 + tp) * VV + v0 + vi]     = __float2half_rn(acc0);
    g_Th[(k * VV + tok0 + tp + 4) * VV + v0 + vi] = __float2half_rn(acc1);
}

// ---------------------------------------------------------------------------
// Kernel 2: gather-sum. One warp per FOUR consecutive positions (pos0 % 4 == 0,
// so all four are on the same side of the j<4 boundary). 16 table loads are
// front-batched for MLP=16; combine is a pure half2 tree (bias pre-folded).
// ---------------------------------------------------------------------------
__device__ __forceinline__ float4 combine4(const uint2& u0, const uint2& u1,
                                           const uint2& u2, const uint2& u3) {
    __half2 lo = __hadd2(__hadd2(*(const __half2*)&u0.x, *(const __half2*)&u1.x),
                         __hadd2(*(const __half2*)&u2.x, *(const __half2*)&u3.x));
    __half2 hi = __hadd2(__hadd2(*(const __half2*)&u0.y, *(const __half2*)&u1.y),
                         __hadd2(*(const __half2*)&u2.y, *(const __half2*)&u3.y));
    float2 flo = __half22float2(lo);
    float2 fhi = __half22float2(hi);
    return make_float4(flo.x, flo.y, fhi.x, fhi.y);
}

__global__ void __launch_bounds__(256)
ngram_sum_kernel(const int* __restrict__ x,
                 const float* __restrict__ bvec,
                 float* __restrict__ out) {
    const int warp = blockIdx.x * (blockDim.x >> 5) + (threadIdx.x >> 5);
    const int lane = threadIdx.x & 31;
    const int pos0 = warp << 2;               // four consecutive positions
    const int b  = pos0 >> 12;                // / 4096
    const int j0 = pos0 & (LL - 1);           // % 4096 (multiple of 4)

    float4* o = reinterpret_cast<float4*>(out + (size_t)pos0 * VV);

    if (j0 == 0) {                            // positions 0..3: bias only
        float4 bb = reinterpret_cast<const float4*>(bvec)[lane];
        o[lane]      = bb;
        o[32 + lane] = bb;
        o[64 + lane] = bb;
        o[96 + lane] = bb;
        return;
    }

    // tokens t0..t6 cover positions j0..j0+3 (position j0+i uses t[i..i+3])
    const int* xr = x + b * LL + (j0 - NN1);
    int t[7];
#pragma unroll
    for (int i = 0; i < 7; i++) t[i] = __ldg(xr + i);

    const uint2* T = reinterpret_cast<const uint2*>(g_Th);   // 32 uint2 per row
    uint2 r[16];
#pragma unroll
    for (int i = 0; i < 4; i++) {             // position index
#pragma unroll
        for (int k = 0; k < 4; k++) {         // slice index
            r[i * 4 + k] = __ldg(&T[((k * VV + t[i + k]) << 5) + lane]);
        }
    }

    o[lane]      = combine4(r[0],  r[1],  r[2],  r[3]);
    o[32 + lane] = combine4(r[4],  r[5],  r[6],  r[7]);
    o[64 + lane] = combine4(r[8],  r[9],  r[10], r[11]);
    o[96 + lane] = combine4(r[12], r[13], r[14], r[15]);
}

// ---------------------------------------------------------------------------
// Launch. Inputs (metadata order): x(int32 B*L), emb(f32 V*D), W(f32 V*4D),
// b(f32 V). Output: f32 B*L*V.
// ---------------------------------------------------------------------------
extern "C" void kernel_launch(void* const* d_in, const int* in_sizes, int n_in,
                              void* d_out, int out_size) {
    const int*   x    = (const int*)d_in[0];
    const float* emb  = (const float*)d_in[1];
    const float* W    = (const float*)d_in[2];
    const float* bvec = (const float*)d_in[3];
    float* out = (float*)d_out;

    dim3 bgrid(VV / VPB, VV / TPB);            // (8, 16) = 128 blocks
    build_table_kernel<<<bgrid, 256>>>(emb, W, bvec);

    const int positions = BB * LL;             // 131072
    const int warps = positions / 4;           // 32768
    const int blocks = warps / 8;              // 4096 (8 warps/block)
    ngram_sum_kernel<<<blocks, 256>>>(x, bvec, out);
}

// round 5
// speedup vs baseline: 1.6622x; 1.0118x over previous
#include <cuda_runtime.h>
#include <cuda_fp16.h>

// Problem constants (match reference)
#define BB 32
#define LL 4096
#define DD 128
#define NN1 4      // N-1 context slots
#define VV 128

// fp16 lookup table: T[k][tok][v], 4*128*128 halves = 128 KB (L1-resident).
// Bias is pre-folded into the k=0 slice.
__device__ __half g_Th[NN1 * VV * VV];

// ---------------------------------------------------------------------------
// Kernel 1: T[k][tok][v] = sum_d emb[tok][d] * W[v][k*128+d]  (+ b[v] at k=0)
// grid = (8 v-groups, 16 tok-groups, 4 k) = 512 blocks, 128 threads.
// Each block stages its 8 KB W k-slice (16 v-rows x 128 floats) and 8 emb rows
// in smem; thread (vi, tp) computes one (tok, v) dot product.
// ---------------------------------------------------------------------------
#define VPB 16      // v-rows per block
#define TPB 8       // toks per block
#define WPAD 4      // smem row pad (floats)

__global__ void __launch_bounds__(128)
build_table_kernel(const float* __restrict__ emb,
                   const float* __restrict__ W,
                   const float* __restrict__ bvec) {
    const int v0   = blockIdx.x * VPB;
    const int tok0 = blockIdx.y * TPB;
    const int k    = blockIdx.z;

    __shared__ float sw[VPB][DD + WPAD];
    __shared__ float e[TPB][DD + WPAD];

    // W k-slice: rows v0..v0+15, cols k*128..k*128+127 -> 512 float4 (coalesced
    // in 32-float4 row chunks)
#pragma unroll
    for (int i = 0; i < 4; i++) {
        int idx = i * 128 + threadIdx.x;           // 0..511
        int vi  = idx >> 5;                        // 32 float4 per row
        int c   = idx & 31;
        const float4* wsrc = reinterpret_cast<const float4*>(
            W + (size_t)(v0 + vi) * (NN1 * DD) + k * DD);
        *reinterpret_cast<float4*>(&sw[vi][c * 4]) = __ldg(&wsrc[c]);
    }
    // emb rows tok0..tok0+7: 256 float4, 2 per thread (coalesced)
    {
        const float4* esrc = reinterpret_cast<const float4*>(emb + (size_t)tok0 * DD);
#pragma unroll
        for (int i = 0; i < 2; i++) {
            int idx = i * 128 + threadIdx.x;       // 0..255
            float4 ev = __ldg(&esrc[idx]);
            int t = idx >> 5;
            int c = idx & 31;
            *reinterpret_cast<float4*>(&e[t][c * 4]) = ev;
        }
    }
    __syncthreads();

    const int vi = threadIdx.x >> 3;               // 0..15
    const int tp = threadIdx.x & 7;                // 0..7

    float acc = 0.0f;
#pragma unroll
    for (int d = 0; d < DD; d += 4) {
        float4 w  = *reinterpret_cast<const float4*>(&sw[vi][d]);
        float4 ea = *reinterpret_cast<const float4*>(&e[tp][d]);
        acc += w.x * ea.x + w.y * ea.y + w.z * ea.z + w.w * ea.w;
    }
    if (k == 0) acc += __ldg(&bvec[v0 + vi]);

    g_Th[(k * VV + tok0 + tp) * VV + v0 + vi] = __float2half_rn(acc);
}

// ---------------------------------------------------------------------------
// Kernel 2: gather-sum. One warp per TWO consecutive positions (j0 even, so
// both positions fall on the same side of the j<4 boundary). Lane handles
// v = lane*4..lane*4+3 via uint2 (4 fp16) per table row. Pure half2 combine
// tree; bias pre-folded into k=0 slice. Grid exactly covers all positions.
// ---------------------------------------------------------------------------
__device__ __forceinline__ float4 combine4(const uint2& u0, const uint2& u1,
                                           const uint2& u2, const uint2& u3) {
    __half2 lo = __hadd2(__hadd2(*(const __half2*)&u0.x, *(const __half2*)&u1.x),
                         __hadd2(*(const __half2*)&u2.x, *(const __half2*)&u3.x));
    __half2 hi = __hadd2(__hadd2(*(const __half2*)&u0.y, *(const __half2*)&u1.y),
                         __hadd2(*(const __half2*)&u2.y, *(const __half2*)&u3.y));
    float2 flo = __half22float2(lo);
    float2 fhi = __half22float2(hi);
    return make_float4(flo.x, flo.y, fhi.x, fhi.y);
}

__global__ void __launch_bounds__(256)
ngram_sum_kernel(const int* __restrict__ x,
                 const float* __restrict__ bvec,
                 float* __restrict__ out) {
    const int warp = blockIdx.x * (blockDim.x >> 5) + (threadIdx.x >> 5);
    const int lane = threadIdx.x & 31;
    const int pos0 = warp << 1;                 // two consecutive positions
    const int b  = pos0 >> 12;                  // / 4096
    const int j0 = pos0 & (LL - 1);             // % 4096 (even)

    float4* o = reinterpret_cast<float4*>(out + (size_t)pos0 * VV);

    if (j0 < NN1) {                             // j0 in {0,2}: bias only
        float4 bb = reinterpret_cast<const float4*>(bvec)[lane];
        o[lane]      = bb;
        o[32 + lane] = bb;
        return;
    }

    const int* xr = x + b * LL + (j0 - NN1);
    const int t0 = __ldg(xr + 0);
    const int t1 = __ldg(xr + 1);
    const int t2 = __ldg(xr + 2);
    const int t3 = __ldg(xr + 3);
    const int t4 = __ldg(xr + 4);

    const uint2* T = reinterpret_cast<const uint2*>(g_Th);   // 32 uint2 per row
    // position j0: tokens t0..t3; position j0+1: tokens t1..t4
    uint2 a0 = __ldg(&T[((0 * VV + t0) << 5) + lane]);
    uint2 a1 = __ldg(&T[((1 * VV + t1) << 5) + lane]);
    uint2 a2 = __ldg(&T[((2 * VV + t2) << 5) + lane]);
    uint2 a3 = __ldg(&T[((3 * VV + t3) << 5) + lane]);
    uint2 c0 = __ldg(&T[((0 * VV + t1) << 5) + lane]);
    uint2 c1 = __ldg(&T[((1 * VV + t2) << 5) + lane]);
    uint2 c2 = __ldg(&T[((2 * VV + t3) << 5) + lane]);
    uint2 c3 = __ldg(&T[((3 * VV + t4) << 5) + lane]);

    o[lane]      = combine4(a0, a1, a2, a3);
    o[32 + lane] = combine4(c0, c1, c2, c3);
}

// ---------------------------------------------------------------------------
// Launch. Inputs (metadata order): x(int32 B*L), emb(f32 V*D), W(f32 V*4D),
// b(f32 V). Output: f32 B*L*V.
// ---------------------------------------------------------------------------
extern "C" void kernel_launch(void* const* d_in, const int* in_sizes, int n_in,
                              void* d_out, int out_size) {
    const int*   x    = (const int*)d_in[0];
    const float* emb  = (const float*)d_in[1];
    const float* W    = (const float*)d_in[2];
    const float* bvec = (const float*)d_in[3];
    float* out = (float*)d_out;

    dim3 bgrid(VV / VPB, VV / TPB, NN1);        // (8, 16, 4) = 512 blocks
    build_table_kernel<<<bgrid, 128>>>(emb, W, bvec);

    const int positions = BB * LL;              // 131072
    const int warps = positions / 2;            // 65536
    const int blocks = warps / 8;               // 8192 (8 warps/block, exact)
    ngram_sum_kernel<<<blocks, 256>>>(x, bvec, out);
}